// round 4
// baseline (speedup 1.0000x reference)
#include <cuda_runtime.h>
#include <math.h>

// Problem shapes (fixed for this dataset)
#define BB 16
#define NN 2048
#define FF 64
#define EE 24576          // edges per batch (N*M = 2048*12)
#define CC 128            // bond dim
#define TOTAL_E (BB*EE)   // 393216

// Scratch (static device globals — no runtime allocation allowed)
__device__ int   g_count[2][BB][NN];                    // slot-0/1 node histograms
__device__ float g_rden[2][BB][FF];                     // reciprocal L1 denominators
__device__ __align__(16) float g_A[2][BB][NN][CC];      // per-node GEMM results (33.5 MB)
__device__ float g_sum[CC];
__device__ float g_sq[CC];
__device__ __align__(16) float g_scale[CC];
__device__ __align__(16) float g_shift[CC];

// ---------------------------------------------------------------------------
__global__ void zero_kernel() {
    int i = blockIdx.x * blockDim.x + threadIdx.x;
    int* cnt = &g_count[0][0][0];
    if (i < 2 * BB * NN) cnt[i] = 0;
    if (i < CC) { g_sum[i] = 0.f; g_sq[i] = 0.f; }
}

// Histogram of node indices per (batch, slot). adj is int32 (JAX x64-disabled).
__global__ void count_kernel(const int* __restrict__ adj) {
    int stride = gridDim.x * blockDim.x;
    for (int e = blockIdx.x * blockDim.x + threadIdx.x; e < TOTAL_E; e += stride) {
        int b = e / EE;
        int2 ad = *(const int2*)(adj + 2 * (size_t)e);
        atomicAdd(&g_count[0][b][ad.x & (NN - 1)], 1);
        atomicAdd(&g_count[1][b][ad.y & (NN - 1)], 1);
    }
}

// denom_s[b,f] = sum_n count_s[b,n] * |atom[b,n,f]|  -> store reciprocal
__global__ void denom_kernel(const float* __restrict__ atom) {
    int s = blockIdx.x & 1, b = blockIdx.x >> 1;
    int tid = threadIdx.x;
    int f = tid & 63, part = tid >> 6;     // 4 row-partitions x 64 features
    float acc = 0.f;
    const float* ab = atom + (size_t)b * NN * FF;
    for (int n = part; n < NN; n += 4) {
        int c = g_count[s][b][n];
        if (c) acc += (float)c * fabsf(ab[n * FF + f]);
    }
    __shared__ float sh[256];
    sh[tid] = acc;
    __syncthreads();
    if (tid < 64) {
        acc = sh[tid] + sh[tid + 64] + sh[tid + 128] + sh[tid + 192];
        g_rden[s][b][f] = 1.0f / fmaxf(acc, 1e-12f);
    }
}

// A_s[b,n,c] = sum_f atom[b,n,f] * rden_s[b,f] * W[s*64+f, c]
// One block computes a 64x128 tile for one (s,b). Grid = 16*2*32 = 1024.
__global__ void gemm_kernel(const float* __restrict__ atom, const float* __restrict__ W) {
    int bx = blockIdx.x;
    int tile = bx & 31, s = (bx >> 5) & 1, b = bx >> 6;
    int n0 = tile * 64;
    __shared__ float a_sh[64][64];
    __shared__ float w_sh[64][CC];
    __shared__ float rsh[64];
    int tid = threadIdx.x;
    if (tid < 64) rsh[tid] = g_rden[s][b][tid];
    const float* wb = W + s * 64 * CC;
    for (int k = tid; k < 64 * CC; k += 256)
        (&w_sh[0][0])[k] = wb[k];
    __syncthreads();
    const float* ab = atom + ((size_t)b * NN + n0) * FF;
    for (int k = tid; k < 64 * 64; k += 256)
        (&a_sh[0][0])[k] = ab[k] * rsh[k & 63];
    __syncthreads();

    int c4 = (tid & 31) * 4;
    int r8 = (tid >> 5) * 8;
    float acc[8][4];
#pragma unroll
    for (int i = 0; i < 8; i++)
#pragma unroll
        for (int j = 0; j < 4; j++) acc[i][j] = 0.f;

#pragma unroll 8
    for (int f = 0; f < 64; f++) {
        float4 wv = *(const float4*)&w_sh[f][c4];
#pragma unroll
        for (int i = 0; i < 8; i++) {
            float a = a_sh[r8 + i][f];
            acc[i][0] = fmaf(a, wv.x, acc[i][0]);
            acc[i][1] = fmaf(a, wv.y, acc[i][1]);
            acc[i][2] = fmaf(a, wv.z, acc[i][2]);
            acc[i][3] = fmaf(a, wv.w, acc[i][3]);
        }
    }
    float* ob = &g_A[s][b][n0][0];
#pragma unroll
    for (int i = 0; i < 8; i++)
        *(float4*)&ob[(size_t)(r8 + i) * CC + c4] =
            make_float4(acc[i][0], acc[i][1], acc[i][2], acc[i][3]);
}

// Per-channel sum and sum-of-squares of z = A0[i0] + A1[i1] (bias cancels in BN)
__global__ void stats_kernel(const int* __restrict__ adj) {
    int tid = threadIdx.x;
    int lane = tid & 31;
    int warp_g = (blockIdx.x * blockDim.x + tid) >> 5;
    int nw = (gridDim.x * blockDim.x) >> 5;
    float s0 = 0, s1 = 0, s2 = 0, s3 = 0, q0 = 0, q1 = 0, q2 = 0, q3 = 0;
    for (int e = warp_g; e < TOTAL_E; e += nw) {
        int b = e / EE;
        int2 ad = *(const int2*)(adj + 2 * (size_t)e);
        const float4* r0 = (const float4*)g_A[0][b][ad.x & (NN - 1)];
        const float4* r1 = (const float4*)g_A[1][b][ad.y & (NN - 1)];
        float4 v0 = r0[lane], v1 = r1[lane];
        float z;
        z = v0.x + v1.x; s0 += z; q0 += z * z;
        z = v0.y + v1.y; s1 += z; q1 += z * z;
        z = v0.z + v1.z; s2 += z; q2 += z * z;
        z = v0.w + v1.w; s3 += z; q3 += z * z;
    }
    __shared__ float sh[8 * CC];
    int w = tid >> 5;
    sh[w * CC + lane * 4 + 0] = s0;
    sh[w * CC + lane * 4 + 1] = s1;
    sh[w * CC + lane * 4 + 2] = s2;
    sh[w * CC + lane * 4 + 3] = s3;
    __syncthreads();
    if (tid < CC) {
        float t = 0;
#pragma unroll
        for (int i = 0; i < 8; i++) t += sh[i * CC + tid];
        atomicAdd(&g_sum[tid], t);
    }
    __syncthreads();
    sh[w * CC + lane * 4 + 0] = q0;
    sh[w * CC + lane * 4 + 1] = q1;
    sh[w * CC + lane * 4 + 2] = q2;
    sh[w * CC + lane * 4 + 3] = q3;
    __syncthreads();
    if (tid < CC) {
        float t = 0;
#pragma unroll
        for (int i = 0; i < 8; i++) t += sh[i * CC + tid];
        atomicAdd(&g_sq[tid], t);
    }
}

__global__ void finalize_kernel(const float* __restrict__ gamma,
                                const float* __restrict__ beta) {
    int c = threadIdx.x;
    float inv = 1.0f / (float)TOTAL_E;
    float mean = g_sum[c] * inv;
    float var = fmaxf(g_sq[c] * inv - mean * mean, 0.0f);
    float sc = __ldg(&gamma[c]) * rsqrtf(var + 1e-5f);
    g_scale[c] = sc;
    g_shift[c] = __ldg(&beta[c]) - mean * sc;
}

__global__ void out_kernel(const int* __restrict__ adj,
                           float* __restrict__ out) {
    int tid = threadIdx.x;
    int lane = tid & 31;
    int warp_g = (blockIdx.x * blockDim.x + tid) >> 5;
    int nw = (gridDim.x * blockDim.x) >> 5;
    float4 sc = *(const float4*)&g_scale[lane * 4];
    float4 sf = *(const float4*)&g_shift[lane * 4];
    for (int e = warp_g; e < TOTAL_E; e += nw) {
        int b = e / EE;
        int2 ad = *(const int2*)(adj + 2 * (size_t)e);
        const float4* r0 = (const float4*)g_A[0][b][ad.x & (NN - 1)];
        const float4* r1 = (const float4*)g_A[1][b][ad.y & (NN - 1)];
        float4 v0 = r0[lane], v1 = r1[lane];
        float4 o;
        o.x = tanhf((v0.x + v1.x) * sc.x + sf.x);
        o.y = tanhf((v0.y + v1.y) * sc.y + sf.y);
        o.z = tanhf((v0.z + v1.z) * sc.z + sf.z);
        o.w = tanhf((v0.w + v1.w) * sc.w + sf.w);
        *(float4*)(out + (size_t)e * CC + lane * 4) = o;
    }
}

extern "C" void kernel_launch(void* const* d_in, const int* in_sizes, int n_in,
                              void* d_out, int out_size) {
    const float* atom      = (const float*)d_in[0];
    const int*   adj       = (const int*)d_in[1];    // int32 (JAX default x64-off)
    const float* W         = (const float*)d_in[2];
    // d_in[3] (bias) is mathematically cancelled by BatchNorm -> unused
    const float* gamma     = (const float*)d_in[4];
    const float* beta      = (const float*)d_in[5];
    float* out             = (float*)d_out;

    zero_kernel<<<256, 256>>>();
    count_kernel<<<512, 256>>>(adj);
    denom_kernel<<<32, 256>>>(atom);
    gemm_kernel<<<1024, 256>>>(atom, W);
    stats_kernel<<<1184, 256>>>(adj);
    finalize_kernel<<<1, 128>>>(gamma, beta);
    out_kernel<<<1184, 256>>>(adj, out);
}

// round 6
// speedup vs baseline: 1.6480x; 1.6480x over previous
#include <cuda_runtime.h>
#include <math.h>

// Problem shapes (fixed for this dataset)
#define BB 16
#define NN 2048
#define FF 64
#define EE 24576          // edges per batch (N*M = 2048*12)
#define CC 128            // bond dim
#define TOTAL_E (BB*EE)   // 393216

// Edge-pass decomposition: 8192 warps * 48 edges = TOTAL_E exactly
#define EP_BLOCKS 1024
#define EP_WARPS  (EP_BLOCKS * 8)
#define EP_CHUNK  (TOTAL_E / EP_WARPS)     // 48

// Scratch (static device globals — no runtime allocation allowed)
__device__ int   g_count[2][BB][NN];                    // slot-0/1 node histograms
__device__ float g_den[2][BB][FF];                      // L1 denominators (raw sums)
__device__ __align__(16) float g_Wp[2][BB][FF][CC];     // rden-folded weights (1 MB)
__device__ __align__(16) float g_A[2][BB][NN][CC];      // per-node GEMM results (33.5 MB)
__device__ float g_sum[CC];
__device__ float g_sq[CC];
__device__ __align__(16) float g_scale[CC];
__device__ __align__(16) float g_shift[CC];

// ---------------------------------------------------------------------------
__global__ void zero_kernel() {
    int i = blockIdx.x * blockDim.x + threadIdx.x;
    int* cnt = &g_count[0][0][0];
    if (i < 2 * BB * NN) cnt[i] = 0;
    if (i < 2 * BB * FF) (&g_den[0][0][0])[i] = 0.f;
    if (i < CC) { g_sum[i] = 0.f; g_sq[i] = 0.f; }
}

// Histogram of node indices per (batch, slot). adj is int32.
__global__ void count_kernel(const int* __restrict__ adj) {
    int stride = gridDim.x * blockDim.x;
    for (int e = blockIdx.x * blockDim.x + threadIdx.x; e < TOTAL_E; e += stride) {
        int b = e / EE;
        int2 ad = *(const int2*)(adj + 2 * (size_t)e);
        atomicAdd(&g_count[0][b][ad.x & (NN - 1)], 1);
        atomicAdd(&g_count[1][b][ad.y & (NN - 1)], 1);
    }
}

// Partial denominators: grid = 2*16*8 = 256 blocks; each covers 256 nodes.
// den_s[b,f] += sum_n count_s[b,n] * |atom[b,n,f]|
__global__ void denom_kernel(const float* __restrict__ atom) {
    int bx = blockIdx.x;
    int part = bx & 7, b = (bx >> 3) & 15, s = bx >> 7;
    int tid = threadIdx.x;
    int f = tid & 63, sub = tid >> 6;        // 4 row sub-partitions
    int nbase = part * 256;
    float acc = 0.f;
    const float* ab = atom + ((size_t)b * NN + nbase) * FF;
    for (int n = sub; n < 256; n += 4) {
        int c = g_count[s][b][nbase + n];
        if (c) acc += (float)c * fabsf(ab[n * FF + f]);
    }
    __shared__ float sh[256];
    sh[tid] = acc;
    __syncthreads();
    if (tid < 64) {
        acc = sh[tid] + sh[tid + 64] + sh[tid + 128] + sh[tid + 192];
        atomicAdd(&g_den[s][b][f], acc);
    }
}

// W'[s,b][f,c] = W[s*64+f][c] / max(den_s[b,f], 1e-12). Grid = 32 blocks.
__global__ void wprep_kernel(const float* __restrict__ W) {
    int s = blockIdx.x & 1, b = blockIdx.x >> 1;
    int tid = threadIdx.x;
    __shared__ float rsh[FF];
    if (tid < FF) rsh[tid] = 1.0f / fmaxf(g_den[s][b][tid], 1e-12f);
    __syncthreads();
    const float* wb = W + s * FF * CC;
    float* wp = &g_Wp[s][b][0][0];
    for (int k = tid; k < FF * CC; k += 256)
        wp[k] = wb[k] * rsh[k >> 7];
}

// A_s[b,n,c] = sum_f atom[b,n,f] * W'[s,b][f,c]
// One block computes a 64x128 tile for one (s,b). Grid = 1024.
__global__ void gemm_kernel(const float* __restrict__ atom) {
    int bx = blockIdx.x;
    int tile = bx & 31, s = (bx >> 5) & 1, b = bx >> 6;
    int n0 = tile * 64;
    __shared__ __align__(16) float a_sh[64][FF];
    __shared__ __align__(16) float w_sh[FF * CC];
    int tid = threadIdx.x;

    const float* wp = &g_Wp[s][b][0][0];
#pragma unroll
    for (int k = tid * 4; k < FF * CC; k += 1024)
        *(float4*)&w_sh[k] = *(const float4*)&wp[k];
    const float* ab = atom + ((size_t)b * NN + n0) * FF;
#pragma unroll
    for (int k = tid * 4; k < 64 * FF; k += 1024)
        *(float4*)((&a_sh[0][0]) + k) = *(const float4*)(ab + k);
    __syncthreads();

    int c4 = (tid & 31) * 4;     // column slice (broadcast-friendly a reads)
    int r8 = (tid >> 5) * 8;     // row base per warp
    float acc[8][4];
#pragma unroll
    for (int i = 0; i < 8; i++)
#pragma unroll
        for (int j = 0; j < 4; j++) acc[i][j] = 0.f;

#pragma unroll 4
    for (int f0 = 0; f0 < FF; f0 += 4) {
        float4 w0 = *(float4*)&w_sh[(f0 + 0) * CC + c4];
        float4 w1 = *(float4*)&w_sh[(f0 + 1) * CC + c4];
        float4 w2 = *(float4*)&w_sh[(f0 + 2) * CC + c4];
        float4 w3 = *(float4*)&w_sh[(f0 + 3) * CC + c4];
#pragma unroll
        for (int i = 0; i < 8; i++) {
            float4 a = *(float4*)&a_sh[r8 + i][f0];
            acc[i][0] = fmaf(a.x, w0.x, acc[i][0]);
            acc[i][1] = fmaf(a.x, w0.y, acc[i][1]);
            acc[i][2] = fmaf(a.x, w0.z, acc[i][2]);
            acc[i][3] = fmaf(a.x, w0.w, acc[i][3]);
            acc[i][0] = fmaf(a.y, w1.x, acc[i][0]);
            acc[i][1] = fmaf(a.y, w1.y, acc[i][1]);
            acc[i][2] = fmaf(a.y, w1.z, acc[i][2]);
            acc[i][3] = fmaf(a.y, w1.w, acc[i][3]);
            acc[i][0] = fmaf(a.z, w2.x, acc[i][0]);
            acc[i][1] = fmaf(a.z, w2.y, acc[i][1]);
            acc[i][2] = fmaf(a.z, w2.z, acc[i][2]);
            acc[i][3] = fmaf(a.z, w2.w, acc[i][3]);
            acc[i][0] = fmaf(a.w, w3.x, acc[i][0]);
            acc[i][1] = fmaf(a.w, w3.y, acc[i][1]);
            acc[i][2] = fmaf(a.w, w3.z, acc[i][2]);
            acc[i][3] = fmaf(a.w, w3.w, acc[i][3]);
        }
    }
    float* ob = &g_A[s][b][n0][0];
#pragma unroll
    for (int i = 0; i < 8; i++)
        *(float4*)&ob[(size_t)(r8 + i) * CC + c4] =
            make_float4(acc[i][0], acc[i][1], acc[i][2], acc[i][3]);
}

// Per-channel sum and sum-of-squares of z = A0[i0] + A1[i1] (bias cancels in BN)
// Grid fixed: EP_BLOCKS x 256; each warp owns EP_CHUNK contiguous edges.
__global__ void stats_kernel(const int* __restrict__ adj) {
    int tid = threadIdx.x;
    int lane = tid & 31;
    int warp_g = (blockIdx.x * blockDim.x + tid) >> 5;
    int e0 = warp_g * EP_CHUNK;
    float s0 = 0, s1 = 0, s2 = 0, s3 = 0, q0 = 0, q1 = 0, q2 = 0, q3 = 0;
#pragma unroll 4
    for (int k = 0; k < EP_CHUNK; k++) {
        int e = e0 + k;
        int b = e / EE;
        int2 ad = *(const int2*)(adj + 2 * (size_t)e);
        const float4* r0 = (const float4*)g_A[0][b][ad.x & (NN - 1)];
        const float4* r1 = (const float4*)g_A[1][b][ad.y & (NN - 1)];
        float4 v0 = r0[lane], v1 = r1[lane];
        float z;
        z = v0.x + v1.x; s0 += z; q0 += z * z;
        z = v0.y + v1.y; s1 += z; q1 += z * z;
        z = v0.z + v1.z; s2 += z; q2 += z * z;
        z = v0.w + v1.w; s3 += z; q3 += z * z;
    }
    __shared__ float sh[8 * CC];
    int w = tid >> 5;
    sh[w * CC + lane * 4 + 0] = s0;
    sh[w * CC + lane * 4 + 1] = s1;
    sh[w * CC + lane * 4 + 2] = s2;
    sh[w * CC + lane * 4 + 3] = s3;
    __syncthreads();
    if (tid < CC) {
        float t = 0;
#pragma unroll
        for (int i = 0; i < 8; i++) t += sh[i * CC + tid];
        atomicAdd(&g_sum[tid], t);
    }
    __syncthreads();
    sh[w * CC + lane * 4 + 0] = q0;
    sh[w * CC + lane * 4 + 1] = q1;
    sh[w * CC + lane * 4 + 2] = q2;
    sh[w * CC + lane * 4 + 3] = q3;
    __syncthreads();
    if (tid < CC) {
        float t = 0;
#pragma unroll
        for (int i = 0; i < 8; i++) t += sh[i * CC + tid];
        atomicAdd(&g_sq[tid], t);
    }
}

__global__ void finalize_kernel(const float* __restrict__ gamma,
                                const float* __restrict__ beta) {
    int c = threadIdx.x;
    float inv = 1.0f / (float)TOTAL_E;
    float mean = g_sum[c] * inv;
    float var = fmaxf(g_sq[c] * inv - mean * mean, 0.0f);
    float sc = __ldg(&gamma[c]) * rsqrtf(var + 1e-5f);
    g_scale[c] = sc;
    g_shift[c] = __ldg(&beta[c]) - mean * sc;
}

__global__ void out_kernel(const int* __restrict__ adj,
                           float* __restrict__ out) {
    int tid = threadIdx.x;
    int lane = tid & 31;
    int warp_g = (blockIdx.x * blockDim.x + tid) >> 5;
    int e0 = warp_g * EP_CHUNK;
    float4 sc = *(const float4*)&g_scale[lane * 4];
    float4 sf = *(const float4*)&g_shift[lane * 4];
#pragma unroll 4
    for (int k = 0; k < EP_CHUNK; k++) {
        int e = e0 + k;
        int b = e / EE;
        int2 ad = *(const int2*)(adj + 2 * (size_t)e);
        const float4* r0 = (const float4*)g_A[0][b][ad.x & (NN - 1)];
        const float4* r1 = (const float4*)g_A[1][b][ad.y & (NN - 1)];
        float4 v0 = r0[lane], v1 = r1[lane];
        float4 o;
        o.x = tanhf((v0.x + v1.x) * sc.x + sf.x);
        o.y = tanhf((v0.y + v1.y) * sc.y + sf.y);
        o.z = tanhf((v0.z + v1.z) * sc.z + sf.z);
        o.w = tanhf((v0.w + v1.w) * sc.w + sf.w);
        *(float4*)(out + (size_t)e * CC + lane * 4) = o;
    }
}

extern "C" void kernel_launch(void* const* d_in, const int* in_sizes, int n_in,
                              void* d_out, int out_size) {
    const float* atom      = (const float*)d_in[0];
    const int*   adj       = (const int*)d_in[1];    // int32 (JAX default x64-off)
    const float* W         = (const float*)d_in[2];
    // d_in[3] (bias) is mathematically cancelled by BatchNorm -> unused
    const float* gamma     = (const float*)d_in[4];
    const float* beta      = (const float*)d_in[5];
    float* out             = (float*)d_out;

    zero_kernel<<<257, 256>>>();
    count_kernel<<<512, 256>>>(adj);
    denom_kernel<<<256, 256>>>(atom);
    wprep_kernel<<<32, 256>>>(W);
    gemm_kernel<<<1024, 256>>>(atom);
    stats_kernel<<<EP_BLOCKS, 256>>>(adj);
    finalize_kernel<<<1, 128>>>(gamma, beta);
    out_kernel<<<EP_BLOCKS, 256>>>(adj, out);
}

// round 7
// speedup vs baseline: 1.8570x; 1.1268x over previous
#include <cuda_runtime.h>
#include <cuda_fp16.h>
#include <math.h>

// Problem shapes (fixed for this dataset)
#define BB 16
#define NN 2048
#define FF 64
#define EE 24576          // edges per batch (N*M = 2048*12)
#define CC 128            // bond dim
#define TOTAL_E (BB*EE)   // 393216

#define A_SCALE 16384.0f          // 2^14 — exact; BN is affine-invariant
#define A_INVSCALE (1.0f/16384.0f)

// Edge-pass decomposition: 8192 warps * 48 edges = TOTAL_E exactly
#define EP_BLOCKS 1024
#define EP_WARPS  (EP_BLOCKS * 8)
#define EP_CHUNK  (TOTAL_E / EP_WARPS)     // 48

// Scratch (static device globals — no runtime allocation allowed)
__device__ int    g_count[2][BB][NN];                   // slot-0/1 node histograms
__device__ float  g_den[2][BB][FF];                     // L1 denominators (raw sums)
__device__ __align__(16) __half g_Ah[2][BB][NN][CC];    // scaled fp16 GEMM results (16.7 MB)
__device__ float  g_sum[CC];                            // sums of scaled z'
__device__ float  g_sq[CC];                             // sums of scaled z'^2

// ---------------------------------------------------------------------------
__global__ void zero_kernel() {
    int i = blockIdx.x * blockDim.x + threadIdx.x;
    int* cnt = &g_count[0][0][0];
    if (i < 2 * BB * NN) cnt[i] = 0;
    if (i < 2 * BB * FF) (&g_den[0][0][0])[i] = 0.f;
    if (i < CC) { g_sum[i] = 0.f; g_sq[i] = 0.f; }
}

// Histogram of node indices per (batch, slot). adj is int32.
__global__ void count_kernel(const int* __restrict__ adj) {
    int stride = gridDim.x * blockDim.x;
    for (int e = blockIdx.x * blockDim.x + threadIdx.x; e < TOTAL_E; e += stride) {
        int b = e / EE;
        int2 ad = *(const int2*)(adj + 2 * (size_t)e);
        atomicAdd(&g_count[0][b][ad.x & (NN - 1)], 1);
        atomicAdd(&g_count[1][b][ad.y & (NN - 1)], 1);
    }
}

// Partial denominators: grid = 2*16*8 = 256 blocks; each covers 256 nodes.
__global__ void denom_kernel(const float* __restrict__ atom) {
    int bx = blockIdx.x;
    int part = bx & 7, b = (bx >> 3) & 15, s = bx >> 7;
    int tid = threadIdx.x;
    int f = tid & 63, sub = tid >> 6;        // 4 row sub-partitions
    int nbase = part * 256;
    float acc = 0.f;
    const float* ab = atom + ((size_t)b * NN + nbase) * FF;
    for (int n = sub; n < 256; n += 4) {
        int c = g_count[s][b][nbase + n];
        if (c) acc += (float)c * fabsf(ab[n * FF + f]);
    }
    __shared__ float sh[256];
    sh[tid] = acc;
    __syncthreads();
    if (tid < 64) {
        acc = sh[tid] + sh[tid + 64] + sh[tid + 128] + sh[tid + 192];
        atomicAdd(&g_den[s][b][f], acc);
    }
}

// A'_s[b,n,c] = A_SCALE * sum_f atom[b,n,f] * (W[s*64+f,c] / den_s[b,f])
// One block computes a 64x128 tile for one (s,b). Grid = 1024.
__global__ void gemm_kernel(const float* __restrict__ atom, const float* __restrict__ W) {
    int bx = blockIdx.x;
    int tile = bx & 31, s = (bx >> 5) & 1, b = bx >> 6;
    int n0 = tile * 64;
    __shared__ __align__(16) float a_sh[64][FF];
    __shared__ __align__(16) float w_sh[FF * CC];
    __shared__ float rsh[FF];
    int tid = threadIdx.x;

    if (tid < FF) rsh[tid] = 1.0f / fmaxf(g_den[s][b][tid], 1e-12f);
    __syncthreads();
    const float* wb = W + s * FF * CC;
#pragma unroll
    for (int k = tid * 4; k < FF * CC; k += 1024) {
        float4 wv = *(const float4*)&wb[k];
        float r = rsh[k >> 7];
        wv.x *= r; wv.y *= r; wv.z *= r; wv.w *= r;
        *(float4*)&w_sh[k] = wv;
    }
    const float* ab = atom + ((size_t)b * NN + n0) * FF;
#pragma unroll
    for (int k = tid * 4; k < 64 * FF; k += 1024)
        *(float4*)((&a_sh[0][0]) + k) = *(const float4*)(ab + k);
    __syncthreads();

    int c4 = (tid & 31) * 4;     // column slice
    int r8 = (tid >> 5) * 8;     // row base per warp
    float acc[8][4];
#pragma unroll
    for (int i = 0; i < 8; i++)
#pragma unroll
        for (int j = 0; j < 4; j++) acc[i][j] = 0.f;

#pragma unroll 4
    for (int f0 = 0; f0 < FF; f0 += 4) {
        float4 w0 = *(float4*)&w_sh[(f0 + 0) * CC + c4];
        float4 w1 = *(float4*)&w_sh[(f0 + 1) * CC + c4];
        float4 w2 = *(float4*)&w_sh[(f0 + 2) * CC + c4];
        float4 w3 = *(float4*)&w_sh[(f0 + 3) * CC + c4];
#pragma unroll
        for (int i = 0; i < 8; i++) {
            float4 a = *(float4*)&a_sh[r8 + i][f0];
            acc[i][0] = fmaf(a.x, w0.x, acc[i][0]);
            acc[i][1] = fmaf(a.x, w0.y, acc[i][1]);
            acc[i][2] = fmaf(a.x, w0.z, acc[i][2]);
            acc[i][3] = fmaf(a.x, w0.w, acc[i][3]);
            acc[i][0] = fmaf(a.y, w1.x, acc[i][0]);
            acc[i][1] = fmaf(a.y, w1.y, acc[i][1]);
            acc[i][2] = fmaf(a.y, w1.z, acc[i][2]);
            acc[i][3] = fmaf(a.y, w1.w, acc[i][3]);
            acc[i][0] = fmaf(a.z, w2.x, acc[i][0]);
            acc[i][1] = fmaf(a.z, w2.y, acc[i][1]);
            acc[i][2] = fmaf(a.z, w2.z, acc[i][2]);
            acc[i][3] = fmaf(a.z, w2.w, acc[i][3]);
            acc[i][0] = fmaf(a.w, w3.x, acc[i][0]);
            acc[i][1] = fmaf(a.w, w3.y, acc[i][1]);
            acc[i][2] = fmaf(a.w, w3.z, acc[i][2]);
            acc[i][3] = fmaf(a.w, w3.w, acc[i][3]);
        }
    }
    __half* ob = &g_Ah[s][b][n0][0];
#pragma unroll
    for (int i = 0; i < 8; i++) {
        __half2 h01 = __floats2half2_rn(acc[i][0] * A_SCALE, acc[i][1] * A_SCALE);
        __half2 h23 = __floats2half2_rn(acc[i][2] * A_SCALE, acc[i][3] * A_SCALE);
        uint2 u = make_uint2(*(unsigned*)&h01, *(unsigned*)&h23);
        *(uint2*)&ob[(size_t)(r8 + i) * CC + c4] = u;
    }
}

// Per-channel sum and sum-of-squares of z' = A'0[i0] + A'1[i1]
__global__ void stats_kernel(const int* __restrict__ adj) {
    int tid = threadIdx.x;
    int lane = tid & 31;
    int warp_g = (blockIdx.x * blockDim.x + tid) >> 5;
    int e0 = warp_g * EP_CHUNK;
    float s0 = 0, s1 = 0, s2 = 0, s3 = 0, q0 = 0, q1 = 0, q2 = 0, q3 = 0;
#pragma unroll 4
    for (int k = 0; k < EP_CHUNK; k++) {
        int e = e0 + k;
        int b = e / EE;
        int2 ad = *(const int2*)(adj + 2 * (size_t)e);
        const uint2* r0 = (const uint2*)g_Ah[0][b][ad.x & (NN - 1)];
        const uint2* r1 = (const uint2*)g_Ah[1][b][ad.y & (NN - 1)];
        uint2 u0 = r0[lane], u1 = r1[lane];
        float2 a0 = __half22float2(*(__half2*)&u0.x);
        float2 a1 = __half22float2(*(__half2*)&u0.y);
        float2 b0 = __half22float2(*(__half2*)&u1.x);
        float2 b1 = __half22float2(*(__half2*)&u1.y);
        float z;
        z = a0.x + b0.x; s0 += z; q0 += z * z;
        z = a0.y + b0.y; s1 += z; q1 += z * z;
        z = a1.x + b1.x; s2 += z; q2 += z * z;
        z = a1.y + b1.y; s3 += z; q3 += z * z;
    }
    __shared__ float sh[8 * CC];
    int w = tid >> 5;
    sh[w * CC + lane * 4 + 0] = s0;
    sh[w * CC + lane * 4 + 1] = s1;
    sh[w * CC + lane * 4 + 2] = s2;
    sh[w * CC + lane * 4 + 3] = s3;
    __syncthreads();
    if (tid < CC) {
        float t = 0;
#pragma unroll
        for (int i = 0; i < 8; i++) t += sh[i * CC + tid];
        atomicAdd(&g_sum[tid], t);
    }
    __syncthreads();
    sh[w * CC + lane * 4 + 0] = q0;
    sh[w * CC + lane * 4 + 1] = q1;
    sh[w * CC + lane * 4 + 2] = q2;
    sh[w * CC + lane * 4 + 3] = q3;
    __syncthreads();
    if (tid < CC) {
        float t = 0;
#pragma unroll
        for (int i = 0; i < 8; i++) t += sh[i * CC + tid];
        atomicAdd(&g_sq[tid], t);
    }
}

// Final pass: gather, BN (finalize folded in), tanh, store.
__global__ void out_kernel(const int* __restrict__ adj,
                           const float* __restrict__ gamma,
                           const float* __restrict__ beta,
                           float* __restrict__ out) {
    __shared__ __align__(16) float ssc[CC];
    __shared__ __align__(16) float ssf[CC];
    int tid = threadIdx.x;
    if (tid < CC) {
        // stats were accumulated on z' = 2^14 z; unscale exactly before eps.
        float inv = 1.0f / (float)TOTAL_E;
        float mean_u = g_sum[tid] * inv * A_INVSCALE;
        float ez2_u  = g_sq[tid] * inv * (A_INVSCALE * A_INVSCALE);
        float var = fmaxf(ez2_u - mean_u * mean_u, 0.0f);
        float sc = __ldg(&gamma[tid]) * rsqrtf(var + 1e-5f);
        ssc[tid] = sc * A_INVSCALE;              // applied to scaled z'
        ssf[tid] = __ldg(&beta[tid]) - mean_u * sc;
    }
    __syncthreads();
    int lane = tid & 31;
    int warp_g = (blockIdx.x * blockDim.x + tid) >> 5;
    int e0 = warp_g * EP_CHUNK;
    float4 sc = *(const float4*)&ssc[lane * 4];
    float4 sf = *(const float4*)&ssf[lane * 4];
#pragma unroll 4
    for (int k = 0; k < EP_CHUNK; k++) {
        int e = e0 + k;
        int b = e / EE;
        int2 ad = *(const int2*)(adj + 2 * (size_t)e);
        const uint2* r0 = (const uint2*)g_Ah[0][b][ad.x & (NN - 1)];
        const uint2* r1 = (const uint2*)g_Ah[1][b][ad.y & (NN - 1)];
        uint2 u0 = r0[lane], u1 = r1[lane];
        float2 a0 = __half22float2(*(__half2*)&u0.x);
        float2 a1 = __half22float2(*(__half2*)&u0.y);
        float2 b0 = __half22float2(*(__half2*)&u1.x);
        float2 b1 = __half22float2(*(__half2*)&u1.y);
        float4 o;
        o.x = tanhf((a0.x + b0.x) * sc.x + sf.x);
        o.y = tanhf((a0.y + b0.y) * sc.y + sf.y);
        o.z = tanhf((a1.x + b1.x) * sc.z + sf.z);
        o.w = tanhf((a1.y + b1.y) * sc.w + sf.w);
        *(float4*)(out + (size_t)e * CC + lane * 4) = o;
    }
}

extern "C" void kernel_launch(void* const* d_in, const int* in_sizes, int n_in,
                              void* d_out, int out_size) {
    const float* atom      = (const float*)d_in[0];
    const int*   adj       = (const int*)d_in[1];    // int32 (JAX default x64-off)
    const float* W         = (const float*)d_in[2];
    // d_in[3] (bias) is mathematically cancelled by BatchNorm -> unused
    const float* gamma     = (const float*)d_in[4];
    const float* beta      = (const float*)d_in[5];
    float* out             = (float*)d_out;

    zero_kernel<<<257, 256>>>();
    count_kernel<<<512, 256>>>(adj);
    denom_kernel<<<256, 256>>>(atom);
    gemm_kernel<<<1024, 256>>>(atom, W);
    stats_kernel<<<EP_BLOCKS, 256>>>(adj);
    out_kernel<<<EP_BLOCKS, 256>>>(adj, gamma, beta, out);
}

// round 8
// speedup vs baseline: 1.9979x; 1.0759x over previous
#include <cuda_runtime.h>
#include <cuda_fp16.h>
#include <math.h>

// Problem shapes (fixed for this dataset)
#define BB 16
#define NN 2048
#define FF 64
#define EE 24576          // edges per batch (N*M = 2048*12)
#define CC 128            // bond dim
#define TOTAL_E (BB*EE)   // 393216

#define A_SCALE 16384.0f          // 2^14 — exact; BN is affine-invariant
#define A_INVSCALE (1.0f/16384.0f)

// Edge-pass decomposition: 8192 warps * 48 edges = TOTAL_E exactly
#define EP_BLOCKS 1024
#define EP_WARPS  (EP_BLOCKS * 8)
#define EP_CHUNK  (TOTAL_E / EP_WARPS)     // 48

// Scratch (static device globals — no runtime allocation allowed)
__device__ int    g_count[2][BB][NN];                   // slot-0/1 node histograms
__device__ float  g_den[2][BB][FF];                     // L1 denominators (raw sums)
__device__ __align__(16) __half g_Ah[2][BB][NN][CC];    // scaled fp16 GEMM results (16.7 MB)
__device__ float  g_sum[CC];                            // sums of scaled z'
__device__ float  g_sq[CC];                             // sums of scaled z'^2

// ---- Blackwell packed-f32 helpers -----------------------------------------
__device__ __forceinline__ void ffma2(unsigned long long& d,
                                      unsigned long long a, unsigned long long b) {
    asm("fma.rn.f32x2 %0, %1, %2, %0;" : "+l"(d) : "l"(a), "l"(b));
}
__device__ __forceinline__ unsigned long long pack2(float x) {
    unsigned long long r;
    asm("mov.b64 %0, {%1, %1};" : "=l"(r) : "f"(x));
    return r;
}
__device__ __forceinline__ float2 unpack2(unsigned long long v) {
    float2 f;
    asm("mov.b64 {%0, %1}, %2;" : "=f"(f.x), "=f"(f.y) : "l"(v));
    return f;
}
__device__ __forceinline__ float tanh_fast(float x) {
    asm("tanh.approx.f32 %0, %0;" : "+f"(x));
    return x;
}

// ---------------------------------------------------------------------------
__global__ void zero_kernel() {
    int i = blockIdx.x * blockDim.x + threadIdx.x;
    int* cnt = &g_count[0][0][0];
    if (i < 2 * BB * NN) cnt[i] = 0;
    if (i < 2 * BB * FF) (&g_den[0][0][0])[i] = 0.f;
    if (i < CC) { g_sum[i] = 0.f; g_sq[i] = 0.f; }
}

// Histogram of node indices per (batch, slot). adj is int32.
__global__ void count_kernel(const int* __restrict__ adj) {
    int stride = gridDim.x * blockDim.x;
    for (int e = blockIdx.x * blockDim.x + threadIdx.x; e < TOTAL_E; e += stride) {
        int b = e / EE;
        int2 ad = *(const int2*)(adj + 2 * (size_t)e);
        atomicAdd(&g_count[0][b][ad.x & (NN - 1)], 1);
        atomicAdd(&g_count[1][b][ad.y & (NN - 1)], 1);
    }
}

// Both-slot partial denominators: grid = 16*8 = 128 blocks, 256 nodes each.
// Single atom read feeds both slot accumulators.
__global__ void denom_kernel(const float* __restrict__ atom) {
    int bx = blockIdx.x;
    int part = bx & 7, b = bx >> 3;
    int tid = threadIdx.x;
    int f = tid & 63, sub = tid >> 6;        // 4 row sub-partitions
    int nbase = part * 256;
    float acc0 = 0.f, acc1 = 0.f;
    const float* ab = atom + ((size_t)b * NN + nbase) * FF;
    for (int n = sub; n < 256; n += 4) {
        float v = fabsf(ab[n * FF + f]);
        int c0 = g_count[0][b][nbase + n];
        int c1 = g_count[1][b][nbase + n];
        acc0 += (float)c0 * v;
        acc1 += (float)c1 * v;
    }
    __shared__ float sh[2][256];
    sh[0][tid] = acc0;
    sh[1][tid] = acc1;
    __syncthreads();
    if (tid < 64) {
        float t = sh[0][tid] + sh[0][tid + 64] + sh[0][tid + 128] + sh[0][tid + 192];
        atomicAdd(&g_den[0][b][tid], t);
    } else if (tid < 128) {
        int ff = tid - 64;
        float t = sh[1][ff] + sh[1][ff + 64] + sh[1][ff + 128] + sh[1][ff + 192];
        atomicAdd(&g_den[1][b][ff], t);
    }
}

// A'_s[b,n,c] = A_SCALE * sum_f atom[b,n,f] * (W[s*64+f,c] / den_s[b,f])
// One block computes a 64x128 tile for one (s,b). Grid = 1024.
// Inner product uses packed fma.rn.f32x2 (2 channels per b64 register).
__global__ void gemm_kernel(const float* __restrict__ atom, const float* __restrict__ W) {
    int bx = blockIdx.x;
    int tile = bx & 31, s = (bx >> 5) & 1, b = bx >> 6;
    int n0 = tile * 64;
    __shared__ __align__(16) float a_sh[64][FF];
    __shared__ __align__(16) float w_sh[FF * CC];
    __shared__ float rsh[FF];
    int tid = threadIdx.x;

    if (tid < FF) rsh[tid] = 1.0f / fmaxf(g_den[s][b][tid], 1e-12f);
    __syncthreads();
    const float* wb = W + s * FF * CC;
#pragma unroll
    for (int k = tid * 4; k < FF * CC; k += 1024) {
        float4 wv = *(const float4*)&wb[k];
        float r = rsh[k >> 7];
        wv.x *= r; wv.y *= r; wv.z *= r; wv.w *= r;
        *(float4*)&w_sh[k] = wv;
    }
    const float* ab = atom + ((size_t)b * NN + n0) * FF;
#pragma unroll
    for (int k = tid * 4; k < 64 * FF; k += 1024)
        *(float4*)((&a_sh[0][0]) + k) = *(const float4*)(ab + k);
    __syncthreads();

    int c4 = (tid & 31) * 4;     // column slice (4 channels = 2 packed pairs)
    int r8 = (tid >> 5) * 8;     // row base per warp
    unsigned long long acc0[8], acc1[8];   // acc0: ch (c4,c4+1), acc1: (c4+2,c4+3)
#pragma unroll
    for (int i = 0; i < 8; i++) { acc0[i] = 0ULL; acc1[i] = 0ULL; }

#pragma unroll 4
    for (int f0 = 0; f0 < FF; f0 += 4) {
        ulonglong2 w0 = *(ulonglong2*)&w_sh[(f0 + 0) * CC + c4];
        ulonglong2 w1 = *(ulonglong2*)&w_sh[(f0 + 1) * CC + c4];
        ulonglong2 w2 = *(ulonglong2*)&w_sh[(f0 + 2) * CC + c4];
        ulonglong2 w3 = *(ulonglong2*)&w_sh[(f0 + 3) * CC + c4];
#pragma unroll
        for (int i = 0; i < 8; i++) {
            float4 a = *(float4*)&a_sh[r8 + i][f0];
            unsigned long long ax = pack2(a.x), ay = pack2(a.y);
            unsigned long long az = pack2(a.z), aw = pack2(a.w);
            ffma2(acc0[i], ax, w0.x); ffma2(acc1[i], ax, w0.y);
            ffma2(acc0[i], ay, w1.x); ffma2(acc1[i], ay, w1.y);
            ffma2(acc0[i], az, w2.x); ffma2(acc1[i], az, w2.y);
            ffma2(acc0[i], aw, w3.x); ffma2(acc1[i], aw, w3.y);
        }
    }
    __half* ob = &g_Ah[s][b][n0][0];
#pragma unroll
    for (int i = 0; i < 8; i++) {
        float2 p0 = unpack2(acc0[i]);
        float2 p1 = unpack2(acc1[i]);
        __half2 h01 = __floats2half2_rn(p0.x * A_SCALE, p0.y * A_SCALE);
        __half2 h23 = __floats2half2_rn(p1.x * A_SCALE, p1.y * A_SCALE);
        uint2 u = make_uint2(*(unsigned*)&h01, *(unsigned*)&h23);
        *(uint2*)&ob[(size_t)(r8 + i) * CC + c4] = u;
    }
}

// Per-channel sum and sum-of-squares of z' = A'0[i0] + A'1[i1]
__global__ void stats_kernel(const int* __restrict__ adj) {
    int tid = threadIdx.x;
    int lane = tid & 31;
    int warp_g = (blockIdx.x * blockDim.x + tid) >> 5;
    int e0 = warp_g * EP_CHUNK;
    float s0 = 0, s1 = 0, s2 = 0, s3 = 0, q0 = 0, q1 = 0, q2 = 0, q3 = 0;
#pragma unroll 4
    for (int k = 0; k < EP_CHUNK; k++) {
        int e = e0 + k;
        int b = e / EE;
        int2 ad = *(const int2*)(adj + 2 * (size_t)e);
        const uint2* r0 = (const uint2*)g_Ah[0][b][ad.x & (NN - 1)];
        const uint2* r1 = (const uint2*)g_Ah[1][b][ad.y & (NN - 1)];
        uint2 u0 = r0[lane], u1 = r1[lane];
        float2 a0 = __half22float2(*(__half2*)&u0.x);
        float2 a1 = __half22float2(*(__half2*)&u0.y);
        float2 b0 = __half22float2(*(__half2*)&u1.x);
        float2 b1 = __half22float2(*(__half2*)&u1.y);
        float z;
        z = a0.x + b0.x; s0 += z; q0 = fmaf(z, z, q0);
        z = a0.y + b0.y; s1 += z; q1 = fmaf(z, z, q1);
        z = a1.x + b1.x; s2 += z; q2 = fmaf(z, z, q2);
        z = a1.y + b1.y; s3 += z; q3 = fmaf(z, z, q3);
    }
    __shared__ float sh[8 * CC];
    int w = tid >> 5;
    sh[w * CC + lane * 4 + 0] = s0;
    sh[w * CC + lane * 4 + 1] = s1;
    sh[w * CC + lane * 4 + 2] = s2;
    sh[w * CC + lane * 4 + 3] = s3;
    __syncthreads();
    if (tid < CC) {
        float t = 0;
#pragma unroll
        for (int i = 0; i < 8; i++) t += sh[i * CC + tid];
        atomicAdd(&g_sum[tid], t);
    }
    __syncthreads();
    sh[w * CC + lane * 4 + 0] = q0;
    sh[w * CC + lane * 4 + 1] = q1;
    sh[w * CC + lane * 4 + 2] = q2;
    sh[w * CC + lane * 4 + 3] = q3;
    __syncthreads();
    if (tid < CC) {
        float t = 0;
#pragma unroll
        for (int i = 0; i < 8; i++) t += sh[i * CC + tid];
        atomicAdd(&g_sq[tid], t);
    }
}

// Final pass: gather, BN (finalize folded in), tanh.approx, store.
__global__ void out_kernel(const int* __restrict__ adj,
                           const float* __restrict__ gamma,
                           const float* __restrict__ beta,
                           float* __restrict__ out) {
    __shared__ __align__(16) float ssc[CC];
    __shared__ __align__(16) float ssf[CC];
    int tid = threadIdx.x;
    if (tid < CC) {
        // stats were accumulated on z' = 2^14 z; unscale exactly before eps.
        float inv = 1.0f / (float)TOTAL_E;
        float mean_u = g_sum[tid] * inv * A_INVSCALE;
        float ez2_u  = g_sq[tid] * inv * (A_INVSCALE * A_INVSCALE);
        float var = fmaxf(ez2_u - mean_u * mean_u, 0.0f);
        float sc = __ldg(&gamma[tid]) * rsqrtf(var + 1e-5f);
        ssc[tid] = sc * A_INVSCALE;              // applied to scaled z'
        ssf[tid] = __ldg(&beta[tid]) - mean_u * sc;
    }
    __syncthreads();
    int lane = tid & 31;
    int warp_g = (blockIdx.x * blockDim.x + tid) >> 5;
    int e0 = warp_g * EP_CHUNK;
    float4 sc = *(const float4*)&ssc[lane * 4];
    float4 sf = *(const float4*)&ssf[lane * 4];
#pragma unroll 4
    for (int k = 0; k < EP_CHUNK; k++) {
        int e = e0 + k;
        int b = e / EE;
        int2 ad = *(const int2*)(adj + 2 * (size_t)e);
        const uint2* r0 = (const uint2*)g_Ah[0][b][ad.x & (NN - 1)];
        const uint2* r1 = (const uint2*)g_Ah[1][b][ad.y & (NN - 1)];
        uint2 u0 = r0[lane], u1 = r1[lane];
        float2 a0 = __half22float2(*(__half2*)&u0.x);
        float2 a1 = __half22float2(*(__half2*)&u0.y);
        float2 b0 = __half22float2(*(__half2*)&u1.x);
        float2 b1 = __half22float2(*(__half2*)&u1.y);
        float4 o;
        o.x = tanh_fast(fmaf(a0.x + b0.x, sc.x, sf.x));
        o.y = tanh_fast(fmaf(a0.y + b0.y, sc.y, sf.y));
        o.z = tanh_fast(fmaf(a1.x + b1.x, sc.z, sf.z));
        o.w = tanh_fast(fmaf(a1.y + b1.y, sc.w, sf.w));
        *(float4*)(out + (size_t)e * CC + lane * 4) = o;
    }
}

extern "C" void kernel_launch(void* const* d_in, const int* in_sizes, int n_in,
                              void* d_out, int out_size) {
    const float* atom      = (const float*)d_in[0];
    const int*   adj       = (const int*)d_in[1];    // int32 (JAX default x64-off)
    const float* W         = (const float*)d_in[2];
    // d_in[3] (bias) is mathematically cancelled by BatchNorm -> unused
    const float* gamma     = (const float*)d_in[4];
    const float* beta      = (const float*)d_in[5];
    float* out             = (float*)d_out;

    zero_kernel<<<257, 256>>>();
    count_kernel<<<512, 256>>>(adj);
    denom_kernel<<<128, 256>>>(atom);
    gemm_kernel<<<1024, 256>>>(atom, W);
    stats_kernel<<<EP_BLOCKS, 256>>>(adj);
    out_kernel<<<EP_BLOCKS, 256>>>(adj, gamma, beta, out);
}